// round 3
// baseline (speedup 1.0000x reference)
#include <cuda_runtime.h>
#include <cstdint>

#define BQ     32
#define NKEYS  4096
#define DIM    64
#define NQ     8
#define CPB    32         // chunks per batch -> grid 1024
#define CHUNK  128        // keys per CTA
#define KP     68         // padded K/Q row stride (floats), conflict-free
#define PSTR   8          // P row stride (floats), float4-aligned

// ---- global scratch (no allocs allowed) ----
__device__ float    g_pv[BQ * CPB * NQ * DIM];   // 2 MB partial PV
__device__ float    g_cs[BQ * CPB * NQ];         // partial colsums
__device__ unsigned g_cnt[BQ];                   // last-block counters

// ---- cp.async helpers ----
__device__ __forceinline__ void cp16(uint32_t s, const float* g) {
    asm volatile("cp.async.cg.shared.global [%0], [%1], 16;\n" :: "r"(s), "l"(g));
}
__device__ __forceinline__ void cp_commit() {
    asm volatile("cp.async.commit_group;\n" ::: "memory");
}
__device__ __forceinline__ void cp_wait0() {
    asm volatile("cp.async.wait_group 0;\n" ::: "memory");
}

// ---- smem layout (float offsets) ----
#define OFF_Q   0
#define OFF_K   (NQ * KP)                    // 544
#define K_SZ    (CHUNK * KP)                 // 8704  (4 warps x 32 rows)
#define OFF_P   (OFF_K + K_SZ)               // 9248
#define P_SZ    (CHUNK * PSTR)               // 1024
#define SMEM_FLOATS (OFF_P + P_SZ)           // 10272 floats = 41,088 B -> 5 CTAs/SM
// epilogue overlays the K region (after a barrier):
//   red  = smem[OFF_K .. OFF_K+2048)   4 warps x 8 m x 64 v
//   csred= smem[OFF_K+2048 .. +2080)   4 warps x 8

extern __shared__ float smem[];

__global__ __launch_bounds__(128, 5)
void attn_fused(const float* __restrict__ keys,
                const float* __restrict__ vals,
                const float* __restrict__ query,
                float* __restrict__ out) {
    const int tid  = threadIdx.x;
    const int lane = tid & 31;
    const int warp = tid >> 5;
    const int b     = blockIdx.x >> 5;
    const int chunk = blockIdx.x & 31;
    const int n0    = chunk * CHUNK;
    __shared__ int s_last;

    const uint32_t sbase = (uint32_t)__cvta_generic_to_shared(smem);
    const float* kg = keys + ((size_t)b * NKEYS + n0 + warp * 32) * DIM;

    // ---- per-warp cp.async stage of this warp's 32 K rows (coalesced) ----
    {
        const uint32_t sk = sbase + (uint32_t)((OFF_K + warp * 32 * KP) << 2);
#pragma unroll
        for (int i = 0; i < 16; ++i) {
            int c = i * 32 + lane;              // 0..511 16B chunks
            int r = c >> 4, s = (c & 15) << 2;
            cp16(sk + (uint32_t)((r * KP + s) << 2), kg + r * DIM + s);
        }
        cp_commit();
    }

    // ---- Q into smem (one barrier, once) ----
    {
        int r = tid >> 4, s = (tid & 15) << 2;
        *(float4*)&smem[OFF_Q + r * KP + s] =
            *(const float4*)(query + ((size_t)b * NQ + r) * DIM + s);
    }
    __syncthreads();

    cp_wait0();
    __syncwarp();

    // ---------- QK + per-key softmax (4 lanes per key, 2 queries each) ----------
    const int m0 = (lane & 3) << 1;
    const float* Kw  = &smem[OFF_K + warp * 32 * KP];
    const float* Qm0 = &smem[OFF_Q + (m0 + 0) * KP];
    const float* Qm1 = &smem[OFF_Q + (m0 + 1) * KP];
    float* Pw = &smem[OFF_P + warp * 32 * PSTR];

    float cs0 = 0.f, cs1 = 0.f;
#pragma unroll
    for (int pass = 0; pass < 4; ++pass) {
        const int r = pass * 8 + (lane >> 2);
        const float* kr = Kw + r * KP;
        float a0 = 0.f, a1 = 0.f;
#pragma unroll
        for (int d4 = 0; d4 < 16; ++d4) {
            float4 kv = *(const float4*)(kr  + (d4 << 2));
            float4 q0 = *(const float4*)(Qm0 + (d4 << 2));
            float4 q1 = *(const float4*)(Qm1 + (d4 << 2));
            a0 += kv.x * q0.x + kv.y * q0.y + kv.z * q0.z + kv.w * q0.w;
            a1 += kv.x * q1.x + kv.y * q1.y + kv.z * q1.z + kv.w * q1.w;
        }
        a0 *= 0.125f; a1 *= 0.125f;
        float mx = fmaxf(a0, a1);
        mx = fmaxf(mx, __shfl_xor_sync(0xffffffffu, mx, 1));
        mx = fmaxf(mx, __shfl_xor_sync(0xffffffffu, mx, 2));
        float e0 = __expf(a0 - mx), e1 = __expf(a1 - mx);
        float sum = e0 + e1;
        sum += __shfl_xor_sync(0xffffffffu, sum, 1);
        sum += __shfl_xor_sync(0xffffffffu, sum, 2);
        float inv = 1.0f / sum;
        float p0 = e0 * inv + 1e-8f;
        float p1 = e1 * inv + 1e-8f;
        *(float2*)&Pw[r * PSTR + m0] = make_float2(p0, p1);
        cs0 += p0; cs1 += p1;
    }
    __syncwarp();

    // ---------- PV: this warp's 32 keys, V straight from global ----------
    const float* vg = vals + ((size_t)b * NKEYS + n0 + warp * 32) * DIM + (lane << 1);
    float pv[16];
#pragma unroll
    for (int i = 0; i < 16; ++i) pv[i] = 0.f;
#pragma unroll 4
    for (int k = 0; k < 32; ++k) {
        float4 pa = *(const float4*)&Pw[k * PSTR];
        float4 pb = *(const float4*)&Pw[k * PSTR + 4];
        float2 vv = *(const float2*)(vg + k * DIM);
        pv[0]  += pa.x * vv.x; pv[1]  += pa.x * vv.y;
        pv[2]  += pa.y * vv.x; pv[3]  += pa.y * vv.y;
        pv[4]  += pa.z * vv.x; pv[5]  += pa.z * vv.y;
        pv[6]  += pa.w * vv.x; pv[7]  += pa.w * vv.y;
        pv[8]  += pb.x * vv.x; pv[9]  += pb.x * vv.y;
        pv[10] += pb.y * vv.x; pv[11] += pb.y * vv.y;
        pv[12] += pb.z * vv.x; pv[13] += pb.z * vv.y;
        pv[14] += pb.w * vv.x; pv[15] += pb.w * vv.y;
    }

    // ---------- epilogue: reduce 4 warps (K region reused after barrier) ----------
    __syncthreads();
    float* red   = &smem[OFF_K];          // [4][8][64]
    float* csred = &smem[OFF_K + 2048];   // [4][8]

#pragma unroll
    for (int off = 16; off >= 4; off >>= 1) {
        cs0 += __shfl_xor_sync(0xffffffffu, cs0, off);
        cs1 += __shfl_xor_sync(0xffffffffu, cs1, off);
    }
    if (lane < 4) {
        csred[warp * 8 + lane * 2 + 0] = cs0;
        csred[warp * 8 + lane * 2 + 1] = cs1;
    }
#pragma unroll
    for (int m = 0; m < 8; ++m) {
        red[(warp * 8 + m) * 64 + (lane << 1) + 0] = pv[2 * m + 0];
        red[(warp * 8 + m) * 64 + (lane << 1) + 1] = pv[2 * m + 1];
    }
    __syncthreads();

    const int pidx = (b * CPB + chunk) * NQ;
    if (tid < 8) {
        g_cs[pidx + tid] = csred[tid] + csred[8 + tid] + csred[16 + tid] + csred[24 + tid];
    }
#pragma unroll
    for (int j = 0; j < 2; ++j) {
        int idx = tid * 2 + j;            // 0..255 float2 slots
        int m = idx >> 5, v2 = (idx & 31) << 1;
        float s0 = 0.f, s1 = 0.f;
#pragma unroll
        for (int w = 0; w < 4; ++w) {
            s0 += red[(w * 8 + m) * 64 + v2];
            s1 += red[(w * 8 + m) * 64 + v2 + 1];
        }
        float* dst = &g_pv[((size_t)pidx + m) * DIM + v2];
        dst[0] = s0; dst[1] = s1;
    }

    // ---------- fused finalize: last chunk CTA of this batch ----------
    __syncthreads();
    if (tid == 0) {
        __threadfence();
        unsigned old = atomicAdd(&g_cnt[b], 1u);
        s_last = (old == CPB - 1) ? 1 : 0;
    }
    __syncthreads();
    if (s_last) {
        __threadfence();
        int m = tid >> 4, v = (tid & 15) << 2;   // 128 threads x float4 = 512 outputs
        float cs = 0.f;
        float4 acc = make_float4(0.f, 0.f, 0.f, 0.f);
#pragma unroll
        for (int c = 0; c < CPB; ++c) {
            cs += g_cs[(b * CPB + c) * NQ + m];
            float4 p = *(const float4*)&g_pv[((size_t)(b * CPB + c) * NQ + m) * DIM + v];
            acc.x += p.x; acc.y += p.y; acc.z += p.z; acc.w += p.w;
        }
        float inv = 1.0f / cs;
        *(float4*)&out[((size_t)b * NQ + m) * DIM + v] =
            make_float4(acc.x * inv, acc.y * inv, acc.z * inv, acc.w * inv);
        if (tid == 0) g_cnt[b] = 0;   // reset for next graph replay
    }
}

extern "C" void kernel_launch(void* const* d_in, const int* in_sizes, int n_in,
                              void* d_out, int out_size) {
    const float* keys  = (const float*)d_in[0];
    const float* vals  = (const float*)d_in[1];
    const float* query = (const float*)d_in[2];
    float* out = (float*)d_out;

    cudaFuncSetAttribute(attn_fused,
                         cudaFuncAttributeMaxDynamicSharedMemorySize,
                         SMEM_FLOATS * sizeof(float));
    attn_fused<<<BQ * CPB, 128, SMEM_FLOATS * sizeof(float)>>>(keys, vals, query, out);
}

// round 4
// speedup vs baseline: 1.2394x; 1.2394x over previous
#include <cuda_runtime.h>
#include <cstdint>

#define BQ     32
#define NKEYS  4096
#define DIM    64
#define NQ     8
#define CPB    16         // chunks per batch -> grid 512
#define CHUNK  256        // keys per CTA (4 warps x 64)
#define WKEYS  64         // keys per warp
#define TKEYS  16         // keys per warp-tile
#define NT     4          // tiles per warp
#define KP     68         // padded K/Q row stride (floats)

typedef unsigned long long u64;

// ---- global scratch (no allocs allowed) ----
__device__ float    g_pv[BQ * CPB * NQ * DIM];
__device__ float    g_cs[BQ * CPB * NQ];
__device__ unsigned g_cnt[BQ];

// ---- cp.async helpers ----
__device__ __forceinline__ void cp16(uint32_t s, const float* g) {
    asm volatile("cp.async.cg.shared.global [%0], [%1], 16;\n" :: "r"(s), "l"(g));
}
__device__ __forceinline__ void cp_commit() {
    asm volatile("cp.async.commit_group;\n" ::: "memory");
}
template <int N>
__device__ __forceinline__ void cp_wait() {
    asm volatile("cp.async.wait_group %0;\n" :: "n"(N) : "memory");
}

// ---- packed f32x2 FMA (Blackwell FFMA2) ----
__device__ __forceinline__ void fma2(u64& d, u64 a, u64 b) {
    asm("fma.rn.f32x2 %0, %1, %2, %0;" : "+l"(d) : "l"(a), "l"(b));
}
__device__ __forceinline__ float f2lo(u64 x) { return __uint_as_float((unsigned)x); }
__device__ __forceinline__ float f2hi(u64 x) { return __uint_as_float((unsigned)(x >> 32)); }

// ---- smem layout (float offsets) ----
// Q: 8 x KP at 0 (544)
// per-warp region (W_SZ floats): K 2 bufs (16xKP each), V 2 bufs (16x64), P (16x16 splatted)
#define W_KSZ   (TKEYS * KP)          // 1088
#define W_VSZ   (TKEYS * DIM)         // 1024
#define W_K     0
#define W_V     (2 * W_KSZ)           // 2176
#define W_P     (W_V + 2 * W_VSZ)     // 4224
#define W_SZ    (W_P + TKEYS * 16)    // 4480
#define OFF_Q   0
#define OFF_W(w) (544 + (w) * W_SZ)
#define SMEM_FLOATS (544 + 4 * W_SZ)  // 18464 floats = 73,856 B -> 3 CTAs/SM

extern __shared__ float smem[];

__global__ __launch_bounds__(128, 3)
void attn_fused(const float* __restrict__ keys,
                const float* __restrict__ vals,
                const float* __restrict__ query,
                float* __restrict__ out) {
    const int tid  = threadIdx.x;
    const int lane = tid & 31;
    const int warp = tid >> 5;
    const int b     = blockIdx.x >> 4;
    const int chunk = blockIdx.x & 15;
    const int n0    = chunk * CHUNK;
    __shared__ int s_last;

    const uint32_t sbase = (uint32_t)__cvta_generic_to_shared(smem);
    const uint32_t wK = sbase + (uint32_t)((OFF_W(warp) + W_K) << 2);
    const uint32_t wV = sbase + (uint32_t)((OFF_W(warp) + W_V) << 2);

    const float* kg = keys + ((size_t)b * NKEYS + n0 + warp * WKEYS) * DIM;
    const float* vg = vals + ((size_t)b * NKEYS + n0 + warp * WKEYS) * DIM;

    // ---- stage helper: K+V for tile t into buffer (t&1), one commit group ----
    auto stage = [&](int t) {
        const int buf = t & 1;
        const float* kt = kg + t * TKEYS * DIM;
        const float* vt = vg + t * TKEYS * DIM;
        const uint32_t kd = wK + (uint32_t)((buf * W_KSZ) << 2);
        const uint32_t vd = wV + (uint32_t)((buf * W_VSZ) << 2);
#pragma unroll
        for (int i = 0; i < 8; ++i) {
            int c = i * 32 + lane;               // 0..255 16B chunks
            int r = c >> 4, s = (c & 15) << 2;
            cp16(kd + (uint32_t)((r * KP + s) << 2), kt + r * DIM + s);
        }
#pragma unroll
        for (int i = 0; i < 8; ++i) {
            int c = i * 32 + lane;
            cp16(vd + (uint32_t)(c << 4), vt + c * 4);
        }
        cp_commit();
    };

    stage(0);
    stage(1);

    // ---- Q into smem (once) ----
    {
        int r = tid >> 4, s = (tid & 15) << 2;
        *(float4*)&smem[OFF_Q + r * KP + s] =
            *(const float4*)(query + ((size_t)b * NQ + r) * DIM + s);
    }
    __syncthreads();

    const int key = lane >> 1;            // 0..15 : this lane's key in tile
    const int m0  = (lane & 1) << 2;      // 0 or 4 : query group
    const float* Kme = &smem[OFF_W(warp) + W_K + key * KP];
    float*       Pw  = &smem[OFF_W(warp) + W_P];
    const float* Vw  = &smem[OFF_W(warp) + W_V];

    float cs0 = 0.f, cs1 = 0.f, cs2 = 0.f, cs3 = 0.f;
    u64 pv[8];
#pragma unroll
    for (int i = 0; i < 8; ++i) pv[i] = 0ull;

#pragma unroll
    for (int t = 0; t < NT; ++t) {
        const int buf = t & 1;
        if (t < NT - 1) cp_wait<1>(); else cp_wait<0>();
        __syncwarp();

        // ---------- QK + per-key softmax (2 lanes/key, 4 queries each) ----------
        {
            const float* kr = Kme + buf * W_KSZ;
            u64 acc0 = 0ull, acc1 = 0ull, acc2 = 0ull, acc3 = 0ull;
#pragma unroll
            for (int d4 = 0; d4 < 16; ++d4) {
                ulonglong2 kv = *(const ulonglong2*)(kr + (d4 << 2));
                ulonglong2 q0 = *(const ulonglong2*)&smem[OFF_Q + (m0 + 0) * KP + (d4 << 2)];
                ulonglong2 q1 = *(const ulonglong2*)&smem[OFF_Q + (m0 + 1) * KP + (d4 << 2)];
                ulonglong2 q2 = *(const ulonglong2*)&smem[OFF_Q + (m0 + 2) * KP + (d4 << 2)];
                ulonglong2 q3 = *(const ulonglong2*)&smem[OFF_Q + (m0 + 3) * KP + (d4 << 2)];
                fma2(acc0, kv.x, q0.x); fma2(acc0, kv.y, q0.y);
                fma2(acc1, kv.x, q1.x); fma2(acc1, kv.y, q1.y);
                fma2(acc2, kv.x, q2.x); fma2(acc2, kv.y, q2.y);
                fma2(acc3, kv.x, q3.x); fma2(acc3, kv.y, q3.y);
            }
            float a0 = (f2lo(acc0) + f2hi(acc0)) * 0.125f;
            float a1 = (f2lo(acc1) + f2hi(acc1)) * 0.125f;
            float a2 = (f2lo(acc2) + f2hi(acc2)) * 0.125f;
            float a3 = (f2lo(acc3) + f2hi(acc3)) * 0.125f;

            float mx = fmaxf(fmaxf(a0, a1), fmaxf(a2, a3));
            mx = fmaxf(mx, __shfl_xor_sync(0xffffffffu, mx, 1));
            float e0 = __expf(a0 - mx), e1 = __expf(a1 - mx);
            float e2 = __expf(a2 - mx), e3 = __expf(a3 - mx);
            float sum = e0 + e1 + e2 + e3;
            sum += __shfl_xor_sync(0xffffffffu, sum, 1);
            float inv = 1.0f / sum;
            float p0 = e0 * inv + 1e-8f;
            float p1 = e1 * inv + 1e-8f;
            float p2 = e2 * inv + 1e-8f;
            float p3 = e3 * inv + 1e-8f;
            cs0 += p0; cs1 += p1; cs2 += p2; cs3 += p3;
            // splatted store: p_m at floats [2m, 2m+1]
            *(float4*)&Pw[key * 16 + m0 * 2]     = make_float4(p0, p0, p1, p1);
            *(float4*)&Pw[key * 16 + m0 * 2 + 4] = make_float4(p2, p2, p3, p3);
        }
        __syncwarp();

        // ---------- PV: 16 keys, this lane owns v-pair (2*lane, 2*lane+1) ----------
        {
            const float* vb = Vw + buf * W_VSZ + (lane << 1);
#pragma unroll
            for (int k = 0; k < TKEYS; ++k) {
                u64 vv = *(const u64*)(vb + k * DIM);
                const ulonglong2* pr = (const ulonglong2*)&Pw[k * 16];
                ulonglong2 p01 = pr[0], p23 = pr[1], p45 = pr[2], p67 = pr[3];
                fma2(pv[0], p01.x, vv); fma2(pv[1], p01.y, vv);
                fma2(pv[2], p23.x, vv); fma2(pv[3], p23.y, vv);
                fma2(pv[4], p45.x, vv); fma2(pv[5], p45.y, vv);
                fma2(pv[6], p67.x, vv); fma2(pv[7], p67.y, vv);
            }
        }
        __syncwarp();

        if (t + 2 < NT) stage(t + 2);
    }

    // ---------- epilogue: per-warp partials into own K region ----------
    // layout: red[m][64] at OFF_W(warp)+0, cs[8] at +512
    {
        float* red = &smem[OFF_W(warp)];
#pragma unroll
        for (int m = 0; m < 8; ++m)
            *(float2*)&red[m * 64 + (lane << 1)] = make_float2(f2lo(pv[m]), f2hi(pv[m]));
#pragma unroll
        for (int off = 16; off >= 2; off >>= 1) {
            cs0 += __shfl_xor_sync(0xffffffffu, cs0, off);
            cs1 += __shfl_xor_sync(0xffffffffu, cs1, off);
            cs2 += __shfl_xor_sync(0xffffffffu, cs2, off);
            cs3 += __shfl_xor_sync(0xffffffffu, cs3, off);
        }
        if (lane < 2) {
            red[512 + m0 + 0] = cs0;
            red[512 + m0 + 1] = cs1;
            red[512 + m0 + 2] = cs2;
            red[512 + m0 + 3] = cs3;
        }
    }
    __syncthreads();

    const int pidx = (b * CPB + chunk) * NQ;
    if (tid < 8) {
        float s = 0.f;
#pragma unroll
        for (int w = 0; w < 4; ++w) s += smem[OFF_W(w) + 512 + tid];
        g_cs[pidx + tid] = s;
    }
    {
        int m = tid >> 4, v4 = (tid & 15) << 2;
        float4 s = make_float4(0.f, 0.f, 0.f, 0.f);
#pragma unroll
        for (int w = 0; w < 4; ++w) {
            float4 p = *(const float4*)&smem[OFF_W(w) + m * 64 + v4];
            s.x += p.x; s.y += p.y; s.z += p.z; s.w += p.w;
        }
        *(float4*)&g_pv[((size_t)pidx + m) * DIM + v4] = s;
    }

    // ---------- fused finalize: last chunk CTA of this batch ----------
    __syncthreads();
    if (tid == 0) {
        __threadfence();
        unsigned old = atomicAdd(&g_cnt[b], 1u);
        s_last = (old == CPB - 1) ? 1 : 0;
    }
    __syncthreads();
    if (s_last) {
        __threadfence();
        int m = tid >> 4, v4 = (tid & 15) << 2;
        float cs = 0.f;
        float4 acc = make_float4(0.f, 0.f, 0.f, 0.f);
#pragma unroll
        for (int c = 0; c < CPB; ++c) {
            cs += g_cs[(b * CPB + c) * NQ + m];
            float4 p = *(const float4*)&g_pv[((size_t)(b * CPB + c) * NQ + m) * DIM + v4];
            acc.x += p.x; acc.y += p.y; acc.z += p.z; acc.w += p.w;
        }
        float inv = 1.0f / cs;
        *(float4*)&out[((size_t)b * NQ + m) * DIM + v4] =
            make_float4(acc.x * inv, acc.y * inv, acc.z * inv, acc.w * inv);
        if (tid == 0) g_cnt[b] = 0;   // reset for next graph replay
    }
}

extern "C" void kernel_launch(void* const* d_in, const int* in_sizes, int n_in,
                              void* d_out, int out_size) {
    const float* keys  = (const float*)d_in[0];
    const float* vals  = (const float*)d_in[1];
    const float* query = (const float*)d_in[2];
    float* out = (float*)d_out;

    cudaFuncSetAttribute(attn_fused,
                         cudaFuncAttributeMaxDynamicSharedMemorySize,
                         SMEM_FLOATS * sizeof(float));
    attn_fused<<<BQ * CPB, 128, SMEM_FLOATS * sizeof(float)>>>(keys, vals, query, out);
}

// round 5
// speedup vs baseline: 1.3125x; 1.0590x over previous
#include <cuda_runtime.h>
#include <cstdint>

#define BQ     32
#define NKEYS  4096
#define DIM    64
#define NQ     8
#define CPB    8          // chunks per batch -> grid 256
#define CHUNK  512        // keys per CTA (8 warps x 64)
#define WKEYS  64
#define TKEYS  8          // keys per warp-tile
#define NT     8          // tiles per warp
#define NBUF   3          // ring depth
#define KP     68         // padded K row stride (floats)

typedef unsigned long long u64;

// ---- global scratch ----
__device__ float    g_pv[BQ * CPB * NQ * DIM];
__device__ float    g_cs[BQ * CPB * NQ];
__device__ unsigned g_cnt[BQ];

// ---- cp.async ----
__device__ __forceinline__ void cp16(uint32_t s, const float* g) {
    asm volatile("cp.async.cg.shared.global [%0], [%1], 16;\n" :: "r"(s), "l"(g));
}
__device__ __forceinline__ void cp_commit() {
    asm volatile("cp.async.commit_group;\n" ::: "memory");
}
template <int N>
__device__ __forceinline__ void cp_wait() {
    asm volatile("cp.async.wait_group %0;\n" :: "n"(N) : "memory");
}

// ---- packed f32x2 FMA ----
__device__ __forceinline__ void fma2(u64& d, u64 a, u64 b) {
    asm("fma.rn.f32x2 %0, %1, %2, %0;" : "+l"(d) : "l"(a), "l"(b));
}
__device__ __forceinline__ float f2lo(u64 x) { return __uint_as_float((unsigned)x); }
__device__ __forceinline__ float f2hi(u64 x) { return __uint_as_float((unsigned)(x >> 32)); }

// ---- smem layout (floats) ----
// Q: 8 x KP = 544
// per-warp: K 3 bufs (8 x KP = 544 each) | V 3 bufs (8 x 64 = 512) | P (8 x 16)
#define W_KSZ   (TKEYS * KP)                   // 544
#define W_VSZ   (TKEYS * DIM)                  // 512
#define W_K     0
#define W_V     (NBUF * W_KSZ)                 // 1632
#define W_P     (W_V + NBUF * W_VSZ)           // 3168
#define W_SZ    (W_P + TKEYS * 16)             // 3296
#define OFF_Q   0
#define OFF_W(w) (544 + (w) * W_SZ)
#define SMEM_FLOATS (544 + 8 * W_SZ)           // 26912 floats = 107,648 B -> 2 CTAs/SM

extern __shared__ float smem[];

__global__ __launch_bounds__(256, 2)
void attn_fused(const float* __restrict__ keys,
                const float* __restrict__ vals,
                const float* __restrict__ query,
                float* __restrict__ out) {
    const int tid  = threadIdx.x;
    const int lane = tid & 31;
    const int warp = tid >> 5;
    const int b     = blockIdx.x >> 3;
    const int chunk = blockIdx.x & 7;
    const int n0    = chunk * CHUNK;
    __shared__ int s_last;

    const uint32_t sbase = (uint32_t)__cvta_generic_to_shared(smem);
    const uint32_t wK = sbase + (uint32_t)((OFF_W(warp) + W_K) << 2);
    const uint32_t wV = sbase + (uint32_t)((OFF_W(warp) + W_V) << 2);

    const float* kg = keys + ((size_t)b * NKEYS + n0 + warp * WKEYS) * DIM;
    const float* vg = vals + ((size_t)b * NKEYS + n0 + warp * WKEYS) * DIM;

    // ---- stage tile t into ring buffer t%NBUF (one commit group: 8 cp.async) ----
    auto stage = [&](int t) {
        const int buf = t % NBUF;
        const float* kt = kg + t * TKEYS * DIM;
        const float* vt = vg + t * TKEYS * DIM;
        const uint32_t kd = wK + (uint32_t)((buf * W_KSZ) << 2);
        const uint32_t vd = wV + (uint32_t)((buf * W_VSZ) << 2);
#pragma unroll
        for (int i = 0; i < 4; ++i) {               // K: 128 x 16B chunks
            int c = i * 32 + lane;
            int r = c >> 4, s = (c & 15) << 2;
            cp16(kd + (uint32_t)((r * KP + s) << 2), kt + r * DIM + s);
        }
#pragma unroll
        for (int i = 0; i < 4; ++i) {               // V: 128 x 16B chunks, linear
            int c = i * 32 + lane;
            cp16(vd + (uint32_t)(c << 4), vt + c * 4);
        }
        cp_commit();
    };

    stage(0); stage(1); stage(2);

    // ---- Q into smem ----
    if (tid < 128) {
        int r = tid >> 4, s = (tid & 15) << 2;
        *(float4*)&smem[OFF_Q + r * KP + s] =
            *(const float4*)(query + ((size_t)b * NQ + r) * DIM + s);
    }
    __syncthreads();

    const int key = lane >> 2;            // 0..7 : key within tile
    const int m0  = (lane & 3) << 1;      // 0,2,4,6 : query pair
    const float* Kme = &smem[OFF_W(warp) + W_K + key * KP];
    const float* Vw  = &smem[OFF_W(warp) + W_V];
    float*       Pw  = &smem[OFF_W(warp) + W_P];
    const float* Qa  = &smem[OFF_Q + (m0 + 0) * KP];
    const float* Qb  = &smem[OFF_Q + (m0 + 1) * KP];

    float cs0 = 0.f, cs1 = 0.f;
    u64 pv[8];
#pragma unroll
    for (int i = 0; i < 8; ++i) pv[i] = 0ull;

#pragma unroll 3
    for (int t = 0; t < NT; ++t) {
        const int buf = t % NBUF;
        if (t < NT - 2)       cp_wait<2>();
        else if (t == NT - 2) cp_wait<1>();
        else                  cp_wait<0>();
        __syncwarp();

        // ---- QK + per-key softmax (4 lanes/key, 2 queries each) ----
        {
            const float* kr = Kme + buf * W_KSZ;
            u64 acc0 = 0ull, acc1 = 0ull;
#pragma unroll
            for (int d4 = 0; d4 < 16; ++d4) {
                ulonglong2 kv = *(const ulonglong2*)(kr + (d4 << 2));
                ulonglong2 q0 = *(const ulonglong2*)(Qa + (d4 << 2));
                ulonglong2 q1 = *(const ulonglong2*)(Qb + (d4 << 2));
                fma2(acc0, kv.x, q0.x); fma2(acc0, kv.y, q0.y);
                fma2(acc1, kv.x, q1.x); fma2(acc1, kv.y, q1.y);
            }
            float a0 = (f2lo(acc0) + f2hi(acc0)) * 0.125f;
            float a1 = (f2lo(acc1) + f2hi(acc1)) * 0.125f;

            float mx = fmaxf(a0, a1);
            mx = fmaxf(mx, __shfl_xor_sync(0xffffffffu, mx, 1));
            mx = fmaxf(mx, __shfl_xor_sync(0xffffffffu, mx, 2));
            float e0 = __expf(a0 - mx), e1 = __expf(a1 - mx);
            float sum = e0 + e1;
            sum += __shfl_xor_sync(0xffffffffu, sum, 1);
            sum += __shfl_xor_sync(0xffffffffu, sum, 2);
            float inv = 1.0f / sum;
            float p0 = e0 * inv + 1e-8f;
            float p1 = e1 * inv + 1e-8f;
            cs0 += p0; cs1 += p1;
            // splatted: p_m occupies floats [2m,2m+1] of row key
            *(float4*)&Pw[key * 16 + (m0 << 1)] = make_float4(p0, p0, p1, p1);
        }
        __syncwarp();

        // ---- PV: 8 keys, lane owns v-pair (2*lane) ----
        {
            const float* vb = Vw + buf * W_VSZ + (lane << 1);
#pragma unroll
            for (int k = 0; k < TKEYS; ++k) {
                u64 vv = *(const u64*)(vb + k * DIM);
                const ulonglong2* pr = (const ulonglong2*)&Pw[k * 16];
                ulonglong2 p01 = pr[0], p23 = pr[1], p45 = pr[2], p67 = pr[3];
                fma2(pv[0], p01.x, vv); fma2(pv[1], p01.y, vv);
                fma2(pv[2], p23.x, vv); fma2(pv[3], p23.y, vv);
                fma2(pv[4], p45.x, vv); fma2(pv[5], p45.y, vv);
                fma2(pv[6], p67.x, vv); fma2(pv[7], p67.y, vv);
            }
        }
        __syncwarp();

        if (t + 3 < NT) stage(t + 3);
    }

    // ---- per-warp partials into own region (private until barrier) ----
    {
        float* red = &smem[OFF_W(warp)];
#pragma unroll
        for (int m = 0; m < 8; ++m)
            *(float2*)&red[m * 64 + (lane << 1)] = make_float2(f2lo(pv[m]), f2hi(pv[m]));
        // cs: lanes with same (lane&3) cover all 8 keys -> reduce over xor 4,8,16
#pragma unroll
        for (int off = 16; off >= 4; off >>= 1) {
            cs0 += __shfl_xor_sync(0xffffffffu, cs0, off);
            cs1 += __shfl_xor_sync(0xffffffffu, cs1, off);
        }
        if (lane < 4) {
            red[512 + m0 + 0] = cs0;
            red[512 + m0 + 1] = cs1;
        }
    }
    __syncthreads();

    const int pidx = (b * CPB + chunk) * NQ;
    if (tid < 8) {
        float s = 0.f;
#pragma unroll
        for (int w = 0; w < 8; ++w) s += smem[OFF_W(w) + 512 + tid];
        g_cs[pidx + tid] = s;
    }
    {
        int m = tid >> 5, v2 = (tid & 31) << 1;
        float s0 = 0.f, s1 = 0.f;
#pragma unroll
        for (int w = 0; w < 8; ++w) {
            float2 p = *(const float2*)&smem[OFF_W(w) + m * 64 + v2];
            s0 += p.x; s1 += p.y;
        }
        *(float2*)&g_pv[((size_t)pidx + m) * DIM + v2] = make_float2(s0, s1);
    }

    // ---- fused finalize ----
    __syncthreads();
    if (tid == 0) {
        __threadfence();
        unsigned old = atomicAdd(&g_cnt[b], 1u);
        s_last = (old == CPB - 1) ? 1 : 0;
    }
    __syncthreads();
    if (s_last) {
        __threadfence();
        int m = tid >> 5, v2 = (tid & 31) << 1;
        float cs = 0.f, a0 = 0.f, a1 = 0.f;
#pragma unroll
        for (int c = 0; c < CPB; ++c) {
            cs += g_cs[(b * CPB + c) * NQ + m];
            float2 p = *(const float2*)&g_pv[((size_t)(b * CPB + c) * NQ + m) * DIM + v2];
            a0 += p.x; a1 += p.y;
        }
        float inv = 1.0f / cs;
        *(float2*)&out[((size_t)b * NQ + m) * DIM + v2] = make_float2(a0 * inv, a1 * inv);
        if (tid == 0) g_cnt[b] = 0;   // reset for next graph replay
    }
}

extern "C" void kernel_launch(void* const* d_in, const int* in_sizes, int n_in,
                              void* d_out, int out_size) {
    const float* keys  = (const float*)d_in[0];
    const float* vals  = (const float*)d_in[1];
    const float* query = (const float*)d_in[2];
    float* out = (float*)d_out;

    cudaFuncSetAttribute(attn_fused,
                         cudaFuncAttributeMaxDynamicSharedMemorySize,
                         SMEM_FLOATS * sizeof(float));
    attn_fused<<<BQ * CPB, 256, SMEM_FLOATS * sizeof(float)>>>(keys, vals, query, out);
}